// round 12
// baseline (speedup 1.0000x reference)
#include <cuda_runtime.h>

#define NN 20000
#define EE 50000
#define BB 128
#define HH 64
#define FEATD 28
#define NTYPES 100
#define EDIM 5
#define MPI 3
#define S2S 4

#define TE 128                       // edges/nodes per GEMM tile
#define EDGETILES (EE / TE + EDIM)   // worst-case edge tile count = 395
#define ROOTTILES ((NN + TE - 1) / TE)  // 157
#define GRIDMP (ROOTTILES + EDGETILES)
#define ZTOT (NN * HH / 4)           // float4 count of one h buffer
#define SMAX 160                     // cached h rows per graph in k_s2s_all
#define SA 512                       // smem softmax-weight slots per graph
#define SCB ((EE + 255) / 256)       // scatter blocks in fused front kernel

typedef unsigned long long u64;

// ---------------- scratch (device globals; no allocation allowed) ----------
__device__ float g_hA[NN * HH];
__device__ float g_hB[NN * HH];
__device__ float g_hC[NN * HH];
__device__ float g_Wmat[EDIM * HH * HH];
__device__ float g_WihT[2 * HH * 4 * HH];   // [128][256] transposed W_ih
__device__ float g_WhhT[HH * 4 * HH];       // [64][256]  transposed W_hh
__device__ float g_a[NN];                   // softmax spill (len > SA only)
__device__ int   g_seg[BB + 1];
__device__ int   g_tcnt[EDIM];
__device__ int   g_tptr[EDIM];
__device__ int   g_toff[EDIM + 1];
__device__ int   g_tileoff[EDIM + 1];
__device__ int   g_psrc[EE];
__device__ int   g_pdst[EE];
__device__ int   g_done = 0;

__device__ __forceinline__ float* hsel(int id) {
    return id == 0 ? g_hA : (id == 1 ? g_hB : g_hC);
}

__device__ __forceinline__ void red_v4(float* p, float a, float b, float c, float d) {
    asm volatile("red.global.add.v4.f32 [%0], {%1, %2, %3, %4};"
                 :: "l"(p), "f"(a), "f"(b), "f"(c), "f"(d) : "memory");
}

// pack one float into both lanes of an f32x2
__device__ __forceinline__ u64 pack2(float x) {
    u64 r; asm("mov.b64 %0, {%1, %1};" : "=l"(r) : "f"(x)); return r;
}
// packed dual-fp32 FMA: d = a * b + d  (per 32-bit lane)
__device__ __forceinline__ void fma2(u64& d, u64 a, u64 b) {
    asm("fma.rn.f32x2 %0, %1, %2, %0;" : "+l"(d) : "l"(a), "l"(b));
}
__device__ __forceinline__ float2 unpack2(u64 v) {
    float2 f; asm("mov.b64 {%0, %1}, %2;" : "=f"(f.x), "=f"(f.y) : "l"(v));
    return f;
}

// ======== setup: seg bounds + type hist + (last block) scan ================
__global__ void k_setup(const int* __restrict__ batch,
                        const int* __restrict__ etype) {
    __shared__ int sh[EDIM];
    int tid = threadIdx.x;
    int gid = blockIdx.x * blockDim.x + tid;

    if (tid < EDIM) sh[tid] = 0;

    if (blockIdx.x == 0 && tid <= BB) {
        if (tid == BB) g_seg[BB] = NN;
        else {
            int lo = 0, hi = NN;
            while (lo < hi) {
                int mid = (lo + hi) >> 1;
                if (batch[mid] < tid) lo = mid + 1; else hi = mid;
            }
            g_seg[tid] = lo;
        }
    }
    __syncthreads();

    if (gid < EE) atomicAdd(&sh[etype[gid]], 1);
    __syncthreads();
    if (tid < EDIM) atomicAdd(&g_tcnt[tid], sh[tid]);
    __syncthreads();

    if (tid == 0) {
        __threadfence();
        int old = atomicAdd(&g_done, 1);
        if (old == (int)gridDim.x - 1) {
            int off = 0, toff = 0;
            for (int t = 0; t < EDIM; t++) {
                int n = atomicAdd(&g_tcnt[t], 0);
                g_toff[t] = off;
                g_tileoff[t] = toff;
                g_tptr[t] = off;
                off += n;
                toff += (n + TE - 1) / TE;
                g_tcnt[t] = 0;
            }
            g_toff[EDIM] = off;
            g_tileoff[EDIM] = toff;
            g_done = 0;
        }
    }
}

// ======== fused front: scatter + wmat + weight transposes + embedding ======
__global__ void k_front(const int* __restrict__ etype,
                        const int* __restrict__ src,
                        const int* __restrict__ dst,
                        const float* __restrict__ W_e1,
                        const float* __restrict__ b_e1,
                        const float* __restrict__ W_e2,
                        const float* __restrict__ b_e2,
                        const float* __restrict__ feat,
                        const int* __restrict__ ntype,
                        const float* __restrict__ W_emb,
                        const float* __restrict__ b_emb,
                        const float* __restrict__ W_ih,
                        const float* __restrict__ W_hh) {
    int tid = threadIdx.x;
    if (blockIdx.x < SCB) {
        int e = blockIdx.x * 256 + tid;
        if (e < EE) {
            int pos = atomicAdd(&g_tptr[etype[e]], 1);
            g_psrc[pos] = src[e];
            g_pdst[pos] = dst[e];
        }
    } else if (blockIdx.x < SCB + 64) {
        __shared__ float hr[EDIM][HH];
        __shared__ float part[4][EDIM][HH];
        int wb = blockIdx.x - SCB;
        if (tid < HH) {
#pragma unroll
            for (int t = 0; t < EDIM; t++)
                hr[t][tid] = fmaxf(W_e1[t * HH + tid] + b_e1[tid], 0.f);
        }
        __syncthreads();
        int jc = tid >> 6;
        int c = tid & 63;
        int idx = wb * 64 + c;
        float a0 = 0.f, a1 = 0.f, a2 = 0.f, a3 = 0.f, a4 = 0.f;
#pragma unroll
        for (int jj = 0; jj < 16; jj++) {
            int j = jc * 16 + jj;
            float w = W_e2[j * (HH * HH) + idx];
            a0 += hr[0][j] * w;
            a1 += hr[1][j] * w;
            a2 += hr[2][j] * w;
            a3 += hr[3][j] * w;
            a4 += hr[4][j] * w;
        }
        part[jc][0][c] = a0; part[jc][1][c] = a1; part[jc][2][c] = a2;
        part[jc][3][c] = a3; part[jc][4][c] = a4;
        __syncthreads();
        if (jc == 0) {
            float bb = b_e2[idx];
#pragma unroll
            for (int t = 0; t < EDIM; t++)
                g_Wmat[t * HH * HH + idx] =
                    bb + part[0][t][c] + part[1][t][c] + part[2][t][c] + part[3][t][c];
        }
    } else if (blockIdx.x < SCB + 65) {
        for (int idx = tid; idx < 2 * HH * 4 * HH; idx += 256) {
            int k = idx >> 8;
            int j = idx & 255;
            g_WihT[idx] = W_ih[j * (2 * HH) + k];
        }
    } else if (blockIdx.x < SCB + 66) {
        for (int idx = tid; idx < HH * 4 * HH; idx += 256) {
            int k = idx >> 8;
            int j = idx & 255;
            g_WhhT[idx] = W_hh[j * HH + k];
        }
    } else {
        __shared__ float sf[4][FEATD];
        int blk = blockIdx.x - SCB - 66;      // 0..4999
        int l = tid >> 6;
        int o = tid & 63;
        int node = blk * 4 + l;
        g_hB[blk * 256 + tid] = 0.f;
        if (o < FEATD) sf[l][o] = feat[node * FEATD + o];
        __syncthreads();
        int t = ntype[node];
        float acc = b_emb[o] + W_emb[t * HH + o];
#pragma unroll
        for (int f = 0; f < FEATD; f++)
            acc += sf[l][f] * W_emb[(NTYPES + f) * HH + o];
        g_hA[node * HH + o] = acc;
    }
}

// ======== fused MP iteration: root + edge GEMM tiles =======================
// 8x8 thread tiles computed as 4 row-pairs x 8 outs via packed fma.rn.f32x2.
// h row-pairs load naturally packed (ld.shared.v2.b64 from k-major tile);
// the broadcast w operand is lane-duplicated via mov.b64 (alu pipe, hidden).
__global__ __launch_bounds__(128) void k_mp(int in_id, int out_id, int zero_id,
                                            int iter,
                                            const float* __restrict__ roots,
                                            const float* __restrict__ bias) {
    const float* hin = hsel(in_id);
    float* hout      = hsel(out_id);
    int tid = threadIdx.x;

    if (zero_id >= 0) {
        float4* z = (float4*)hsel(zero_id);
        const int chunk = (ZTOT + GRIDMP - 1) / GRIDMP;
        int lo = blockIdx.x * chunk;
        int hiz = lo + chunk; if (hiz > ZTOT) hiz = ZTOT;
        for (int i = lo + tid; i < hiz; i += 128)
            z[i] = make_float4(0.f, 0.f, 0.f, 0.f);
    }

    __shared__ __align__(16) float hsT[HH][TE + 8];   // [k][row]
    __shared__ __align__(16) float ws[HH * HH];       // [k*64+o]
    __shared__ int sdst[TE];

    bool is_root = blockIdx.x < (unsigned)ROOTTILES;
    const float* W;
    int base;

    if (is_root) {
        base = blockIdx.x * TE;
        W = roots + iter * HH * HH;
        if (tid < TE) {
            int node = base + tid;
            sdst[tid] = (node < NN) ? node : -1;
        }
    } else {
        int tb = blockIdx.x - ROOTTILES;
        if (tb >= g_tileoff[EDIM]) return;
        int t = 0;
        while (tb >= g_tileoff[t + 1]) t++;
        base = g_toff[t] + (tb - g_tileoff[t]) * TE;
        int hi = g_toff[t + 1];
        W = g_Wmat + t * HH * HH;
        if (tid < TE) {
            int p = base + tid;
            sdst[tid] = (p < hi) ? g_pdst[p] : -1;
        }
    }

    for (int i = tid; i < HH * HH; i += 128)
        ws[i] = W[i];

    {
        int s;
        if (is_root) {
            int node = base + tid;
            s = (node < NN) ? node : 0;
        } else {
            int p = base + tid;
            s = (sdst[tid] >= 0) ? g_psrc[p] : 0;
        }
        const float4* hr = (const float4*)(hin + s * HH);
#pragma unroll
        for (int j = 0; j < 16; j++) {
            float4 v = hr[j];
            int k = j * 4;
            hsT[k + 0][tid] = v.x;
            hsT[k + 1][tid] = v.y;
            hsT[k + 2][tid] = v.z;
            hsT[k + 3][tid] = v.w;
        }
    }
    __syncthreads();

    int rg = tid >> 3;   // 0..15 row group (8 rows = 4 row-pairs)
    int og = tid & 7;    // 0..7  out group (8 outs)

    // acc2[ap][b]: f32x2 accumulator for rows (rg*8+2ap, rg*8+2ap+1), out og*8+b
    u64 acc2[4][8];
    if (is_root) {
        float4 b0 = *(const float4*)(bias + iter * HH + og * 8);
        float4 b1 = *(const float4*)(bias + iter * HH + og * 8 + 4);
        float bb[8] = {b0.x, b0.y, b0.z, b0.w, b1.x, b1.y, b1.z, b1.w};
#pragma unroll
        for (int ap = 0; ap < 4; ap++)
#pragma unroll
            for (int b = 0; b < 8; b++) acc2[ap][b] = pack2(bb[b]);
    } else {
#pragma unroll
        for (int ap = 0; ap < 4; ap++)
#pragma unroll
            for (int b = 0; b < 8; b++) acc2[ap][b] = 0ull;
    }

#pragma unroll 4
    for (int k = 0; k < HH; k++) {
        // 4 naturally-packed row pairs (rows are contiguous in hsT[k][*])
        double2 ha = *(const double2*)&hsT[k][rg * 8];
        double2 hb = *(const double2*)&hsT[k][rg * 8 + 4];
        u64 h0 = __double_as_longlong(ha.x);
        u64 h1 = __double_as_longlong(ha.y);
        u64 h2 = __double_as_longlong(hb.x);
        u64 h3 = __double_as_longlong(hb.y);
        // 8 broadcast-packed w values (mov.b64 on alu pipe)
        float4 w0 = *(const float4*)&ws[k * HH + og * 8];
        float4 w1 = *(const float4*)&ws[k * HH + og * 8 + 4];
        u64 wb0 = pack2(w0.x), wb1 = pack2(w0.y), wb2 = pack2(w0.z), wb3 = pack2(w0.w);
        u64 wb4 = pack2(w1.x), wb5 = pack2(w1.y), wb6 = pack2(w1.z), wb7 = pack2(w1.w);

        fma2(acc2[0][0], h0, wb0); fma2(acc2[0][1], h0, wb1);
        fma2(acc2[0][2], h0, wb2); fma2(acc2[0][3], h0, wb3);
        fma2(acc2[0][4], h0, wb4); fma2(acc2[0][5], h0, wb5);
        fma2(acc2[0][6], h0, wb6); fma2(acc2[0][7], h0, wb7);

        fma2(acc2[1][0], h1, wb0); fma2(acc2[1][1], h1, wb1);
        fma2(acc2[1][2], h1, wb2); fma2(acc2[1][3], h1, wb3);
        fma2(acc2[1][4], h1, wb4); fma2(acc2[1][5], h1, wb5);
        fma2(acc2[1][6], h1, wb6); fma2(acc2[1][7], h1, wb7);

        fma2(acc2[2][0], h2, wb0); fma2(acc2[2][1], h2, wb1);
        fma2(acc2[2][2], h2, wb2); fma2(acc2[2][3], h2, wb3);
        fma2(acc2[2][4], h2, wb4); fma2(acc2[2][5], h2, wb5);
        fma2(acc2[2][6], h2, wb6); fma2(acc2[2][7], h2, wb7);

        fma2(acc2[3][0], h3, wb0); fma2(acc2[3][1], h3, wb1);
        fma2(acc2[3][2], h3, wb2); fma2(acc2[3][3], h3, wb3);
        fma2(acc2[3][4], h3, wb4); fma2(acc2[3][5], h3, wb5);
        fma2(acc2[3][6], h3, wb6); fma2(acc2[3][7], h3, wb7);
    }

    // writeback: unpack row pairs, vector atomics
#pragma unroll
    for (int ap = 0; ap < 4; ap++) {
        float2 u0 = unpack2(acc2[ap][0]);
        float2 u1 = unpack2(acc2[ap][1]);
        float2 u2 = unpack2(acc2[ap][2]);
        float2 u3 = unpack2(acc2[ap][3]);
        float2 u4 = unpack2(acc2[ap][4]);
        float2 u5 = unpack2(acc2[ap][5]);
        float2 u6 = unpack2(acc2[ap][6]);
        float2 u7 = unpack2(acc2[ap][7]);
        int dlo = sdst[rg * 8 + 2 * ap];
        int dhi = sdst[rg * 8 + 2 * ap + 1];
        if (dlo >= 0) {
            float* dr = hout + dlo * HH + og * 8;
            red_v4(dr,     u0.x, u1.x, u2.x, u3.x);
            red_v4(dr + 4, u4.x, u5.x, u6.x, u7.x);
        }
        if (dhi >= 0) {
            float* dr = hout + dhi * HH + og * 8;
            red_v4(dr,     u0.y, u1.y, u2.y, u3.y);
            red_v4(dr + 4, u4.y, u5.y, u6.y, u7.y);
        }
    }
}

// ======== fully fused Set2Set: 4 iterations + output MLP ===================
__global__ __launch_bounds__(256) void k_s2s_all(const float* __restrict__ b_ih,
                                                 const float* __restrict__ b_hh,
                                                 const float* __restrict__ W_o1,
                                                 const float* __restrict__ b_o1,
                                                 const float* __restrict__ W_o2,
                                                 const float* __restrict__ b_o2,
                                                 float* __restrict__ out) {
    const float* h = g_hA;          // final node states after MPI=3 (A->B->C->A)
    int b = blockIdx.x;
    int tid = threadIdx.x;

    __shared__ float hcache[SMAX * HH];   // 40KB
    __shared__ float sa[SA];
    __shared__ float qs[2 * HH];
    __shared__ float gates[4 * HH];
    __shared__ float q[HH];
    __shared__ float hx_s[HH];
    __shared__ float cx_s[HH];
    __shared__ float red[256];
    __shared__ float r4[4][HH];

    int s = g_seg[b], t = g_seg[b + 1];
    int len = t - s;
    int nc = len < SMAX ? len : SMAX;

    {
        float4* d4 = (float4*)hcache;
        const float4* s4 = (const float4*)(h + s * HH);
        int tot = nc * (HH / 4);
        for (int i = tid; i < tot; i += 256) d4[i] = s4[i];
    }
    if (tid < 2 * HH) qs[tid] = 0.f;
    if (tid < HH) { hx_s[tid] = 0.f; cx_s[tid] = 0.f; }
    __syncthreads();

    float ev[8];   // per-thread scores (supports len <= 2048)

    for (int it = 0; it < S2S; it++) {
        {
            float g0 = b_ih[tid];
            float g1 = b_hh[tid];
#pragma unroll 8
            for (int k = 0; k < 2 * HH; k++) g0 += qs[k] * g_WihT[k * 256 + tid];
#pragma unroll 8
            for (int k = 0; k < HH; k++)     g1 += hx_s[k] * g_WhhT[k * 256 + tid];
            gates[tid] = g0 + g1;
        }
        __syncthreads();
        if (tid < HH) {
            float ig = gates[tid], fg = gates[HH + tid];
            float gg = gates[2 * HH + tid], og = gates[3 * HH + tid];
            float si = 1.f / (1.f + expf(-ig));
            float sf = 1.f / (1.f + expf(-fg));
            float so = 1.f / (1.f + expf(-og));
            float c = sf * cx_s[tid] + si * tanhf(gg);
            cx_s[tid] = c;
            float hx = so * tanhf(c);
            hx_s[tid] = hx;
            q[tid] = hx;
        }
        __syncthreads();

        float lmax = -1e30f;
        const float4* q4 = (const float4*)q;
        {
            int i = 0;
            for (int l = tid; l < len && i < 8; l += 256, i++) {
                const float4* hr = (l < nc) ? (const float4*)&hcache[l * HH]
                                            : (const float4*)(h + (s + l) * HH);
                float e = 0.f;
#pragma unroll
                for (int k = 0; k < HH / 4; k++) {
                    float4 hv = hr[k];
                    float4 qv = q4[k];
                    e += hv.x * qv.x + hv.y * qv.y + hv.z * qv.z + hv.w * qv.w;
                }
                ev[i] = e;
                lmax = fmaxf(lmax, e);
            }
        }
        red[tid] = lmax; __syncthreads();
        for (int w = 128; w > 0; w >>= 1) {
            if (tid < w) red[tid] = fmaxf(red[tid], red[tid + w]);
            __syncthreads();
        }
        float m = red[0];
        __syncthreads();

        float lsum = 0.f;
        {
            int i = 0;
            for (int l = tid; l < len && i < 8; l += 256, i++) {
                float a = expf(ev[i] - m);
                if (l < SA) sa[l] = a; else g_a[s + l] = a;
                lsum += a;
            }
        }
        red[tid] = lsum; __syncthreads();
        for (int w = 128; w > 0; w >>= 1) {
            if (tid < w) red[tid] += red[tid + w];
            __syncthreads();
        }
        float denom = red[0];
        if (denom == 0.f) denom = 1.f;
        __syncthreads();

        {
            int part = tid >> 6;
            int o = tid & 63;
            float r = 0.f;
            for (int l = part; l < len; l += 4) {
                float av = (l < SA) ? sa[l] : g_a[s + l];
                float hv = (l < nc) ? hcache[l * HH + o] : h[(s + l) * HH + o];
                r += av * hv;
            }
            r4[part][o] = r;
        }
        __syncthreads();
        if (tid < HH) {
            float r = (r4[0][tid] + r4[1][tid] + r4[2][tid] + r4[3][tid]) / denom;
            qs[tid]      = q[tid];
            qs[HH + tid] = r;
        }
        __syncthreads();
    }

    if (tid < HH) {
        float v = b_o1[tid];
#pragma unroll 8
        for (int k = 0; k < 2 * HH; k++) v += qs[k] * W_o1[k * HH + tid];
        v = fmaxf(v, 0.f);
        red[tid] = v * W_o2[tid];
    }
    __syncthreads();
    for (int w = 32; w > 0; w >>= 1) {
        if (tid < w) red[tid] += red[tid + w];
        __syncthreads();
    }
    if (tid == 0) out[b] = red[0] + b_o2[0];
}

// ---------------------------------------------------------------------------
extern "C" void kernel_launch(void* const* d_in, const int* in_sizes, int n_in,
                              void* d_out, int out_size) {
    const float* node_feat = (const float*)d_in[0];
    const int*   node_type = (const int*)d_in[1];
    const int*   edge_index= (const int*)d_in[2];
    const int*   etype     = (const int*)d_in[3];
    const int*   batch     = (const int*)d_in[4];
    const float* W_emb     = (const float*)d_in[5];
    const float* b_emb     = (const float*)d_in[6];
    const float* W_e1      = (const float*)d_in[7];
    const float* b_e1      = (const float*)d_in[8];
    const float* W_e2      = (const float*)d_in[9];
    const float* b_e2      = (const float*)d_in[10];
    const float* roots     = (const float*)d_in[11];
    const float* conv_bias = (const float*)d_in[12];
    const float* W_ih      = (const float*)d_in[13];
    const float* W_hh      = (const float*)d_in[14];
    const float* b_ih      = (const float*)d_in[15];
    const float* b_hh      = (const float*)d_in[16];
    const float* W_o1      = (const float*)d_in[17];
    const float* b_o1      = (const float*)d_in[18];
    const float* W_o2      = (const float*)d_in[19];
    const float* b_o2      = (const float*)d_in[20];
    float* out = (float*)d_out;

    const int* src = edge_index;
    const int* dst = edge_index + EE;

    k_setup<<<(EE + 255) / 256, 256>>>(batch, etype);
    k_front<<<SCB + 66 + NN / 4, 256>>>(etype, src, dst,
                                        W_e1, b_e1, W_e2, b_e2,
                                        node_feat, node_type, W_emb, b_emb,
                                        W_ih, W_hh);

    // 3-buffer rotation: (in, out, zero)
    k_mp<<<GRIDMP, 128>>>(0, 1, 2, 0, roots, conv_bias);  // A->B, zero C
    k_mp<<<GRIDMP, 128>>>(1, 2, 0, 1, roots, conv_bias);  // B->C, zero A
    k_mp<<<GRIDMP, 128>>>(2, 0, -1, 2, roots, conv_bias); // C->A

    k_s2s_all<<<BB, 256>>>(b_ih, b_hh, W_o1, b_o1, W_o2, b_o2, out);
}

// round 13
// speedup vs baseline: 1.0161x; 1.0161x over previous
#include <cuda_runtime.h>

#define NN 20000
#define EE 50000
#define BB 128
#define HH 64
#define FEATD 28
#define NTYPES 100
#define EDIM 5
#define MPI 3
#define S2S 4

#define TE 128                       // edges/nodes per GEMM tile
#define EDGETILES (EE / TE + EDIM)   // worst-case edge tile count = 395
#define ROOTTILES ((NN + TE - 1) / TE)  // 157
#define GRIDMP (ROOTTILES + EDGETILES)
#define ZTOT (NN * HH / 4)           // float4 count of one h buffer
#define SMAX 160                     // cached h rows per graph in k_s2s_all
#define SA 512                       // smem softmax-weight slots per graph
#define SCB ((EE + 255) / 256)       // scatter blocks in fused front kernel

typedef unsigned long long u64;

// ---------------- scratch (device globals; no allocation allowed) ----------
__device__ float g_hA[NN * HH];
__device__ float g_hB[NN * HH];
__device__ float g_hC[NN * HH];
__device__ float g_Wmat[EDIM * HH * HH];
__device__ float g_WihT[2 * HH * 4 * HH];   // [128][256] transposed W_ih
__device__ float g_WhhT[HH * 4 * HH];       // [64][256]  transposed W_hh
__device__ float g_a[NN];                   // softmax spill (len > SA only)
__device__ int   g_seg[BB + 1];
__device__ int   g_tcnt[EDIM];
__device__ int   g_tptr[EDIM];
__device__ int   g_toff[EDIM + 1];
__device__ int   g_tileoff[EDIM + 1];
__device__ int   g_psrc[EE];
__device__ int   g_pdst[EE];
__device__ int   g_done = 0;

__device__ __forceinline__ float* hsel(int id) {
    return id == 0 ? g_hA : (id == 1 ? g_hB : g_hC);
}

__device__ __forceinline__ void red_v4(float* p, float a, float b, float c, float d) {
    asm volatile("red.global.add.v4.f32 [%0], {%1, %2, %3, %4};"
                 :: "l"(p), "f"(a), "f"(b), "f"(c), "f"(d) : "memory");
}

__device__ __forceinline__ u64 pack2(float x) {
    u64 r; asm("mov.b64 %0, {%1, %1};" : "=l"(r) : "f"(x)); return r;
}
__device__ __forceinline__ void fma2(u64& d, u64 a, u64 b) {
    asm("fma.rn.f32x2 %0, %1, %2, %0;" : "+l"(d) : "l"(a), "l"(b));
}
__device__ __forceinline__ float2 unpack2(u64 v) {
    float2 f; asm("mov.b64 {%0, %1}, %2;" : "=f"(f.x), "=f"(f.y) : "l"(v));
    return f;
}

// ======== setup: seg bounds + type hist + (last block) scan ================
__global__ void k_setup(const int* __restrict__ batch,
                        const int* __restrict__ etype) {
    __shared__ int sh[EDIM];
    int tid = threadIdx.x;
    int gid = blockIdx.x * blockDim.x + tid;

    if (tid < EDIM) sh[tid] = 0;

    if (blockIdx.x == 0 && tid <= BB) {
        if (tid == BB) g_seg[BB] = NN;
        else {
            int lo = 0, hi = NN;
            while (lo < hi) {
                int mid = (lo + hi) >> 1;
                if (batch[mid] < tid) lo = mid + 1; else hi = mid;
            }
            g_seg[tid] = lo;
        }
    }
    __syncthreads();

    if (gid < EE) atomicAdd(&sh[etype[gid]], 1);
    __syncthreads();
    if (tid < EDIM) atomicAdd(&g_tcnt[tid], sh[tid]);
    __syncthreads();

    if (tid == 0) {
        __threadfence();
        int old = atomicAdd(&g_done, 1);
        if (old == (int)gridDim.x - 1) {
            int off = 0, toff = 0;
            for (int t = 0; t < EDIM; t++) {
                int n = atomicAdd(&g_tcnt[t], 0);
                g_toff[t] = off;
                g_tileoff[t] = toff;
                g_tptr[t] = off;
                off += n;
                toff += (n + TE - 1) / TE;
                g_tcnt[t] = 0;
            }
            g_toff[EDIM] = off;
            g_tileoff[EDIM] = toff;
            g_done = 0;
        }
    }
}

// ======== fused front: scatter + wmat + weight transposes + embedding ======
__global__ void k_front(const int* __restrict__ etype,
                        const int* __restrict__ src,
                        const int* __restrict__ dst,
                        const float* __restrict__ W_e1,
                        const float* __restrict__ b_e1,
                        const float* __restrict__ W_e2,
                        const float* __restrict__ b_e2,
                        const float* __restrict__ feat,
                        const int* __restrict__ ntype,
                        const float* __restrict__ W_emb,
                        const float* __restrict__ b_emb,
                        const float* __restrict__ W_ih,
                        const float* __restrict__ W_hh) {
    int tid = threadIdx.x;
    if (blockIdx.x < SCB) {
        int e = blockIdx.x * 256 + tid;
        if (e < EE) {
            int pos = atomicAdd(&g_tptr[etype[e]], 1);
            g_psrc[pos] = src[e];
            g_pdst[pos] = dst[e];
        }
    } else if (blockIdx.x < SCB + 64) {
        __shared__ float hr[EDIM][HH];
        __shared__ float part[4][EDIM][HH];
        int wb = blockIdx.x - SCB;
        if (tid < HH) {
#pragma unroll
            for (int t = 0; t < EDIM; t++)
                hr[t][tid] = fmaxf(W_e1[t * HH + tid] + b_e1[tid], 0.f);
        }
        __syncthreads();
        int jc = tid >> 6;
        int c = tid & 63;
        int idx = wb * 64 + c;
        float a0 = 0.f, a1 = 0.f, a2 = 0.f, a3 = 0.f, a4 = 0.f;
#pragma unroll
        for (int jj = 0; jj < 16; jj++) {
            int j = jc * 16 + jj;
            float w = W_e2[j * (HH * HH) + idx];
            a0 += hr[0][j] * w;
            a1 += hr[1][j] * w;
            a2 += hr[2][j] * w;
            a3 += hr[3][j] * w;
            a4 += hr[4][j] * w;
        }
        part[jc][0][c] = a0; part[jc][1][c] = a1; part[jc][2][c] = a2;
        part[jc][3][c] = a3; part[jc][4][c] = a4;
        __syncthreads();
        if (jc == 0) {
            float bb = b_e2[idx];
#pragma unroll
            for (int t = 0; t < EDIM; t++)
                g_Wmat[t * HH * HH + idx] =
                    bb + part[0][t][c] + part[1][t][c] + part[2][t][c] + part[3][t][c];
        }
    } else if (blockIdx.x < SCB + 65) {
        for (int idx = tid; idx < 2 * HH * 4 * HH; idx += 256) {
            int k = idx >> 8;
            int j = idx & 255;
            g_WihT[idx] = W_ih[j * (2 * HH) + k];
        }
    } else if (blockIdx.x < SCB + 66) {
        for (int idx = tid; idx < HH * 4 * HH; idx += 256) {
            int k = idx >> 8;
            int j = idx & 255;
            g_WhhT[idx] = W_hh[j * HH + k];
        }
    } else {
        __shared__ float sf[4][FEATD];
        int blk = blockIdx.x - SCB - 66;      // 0..4999
        int l = tid >> 6;
        int o = tid & 63;
        int node = blk * 4 + l;
        g_hB[blk * 256 + tid] = 0.f;
        if (o < FEATD) sf[l][o] = feat[node * FEATD + o];
        __syncthreads();
        int t = ntype[node];
        float acc = b_emb[o] + W_emb[t * HH + o];
#pragma unroll
        for (int f = 0; f < FEATD; f++)
            acc += sf[l][f] * W_emb[(NTYPES + f) * HH + o];
        g_hA[node * HH + o] = acc;
    }
}

// ======== fused MP iteration: root + edge GEMM tiles =======================
// Changes vs prev round:
//  - W is read directly from global in the compute loop (L1-resident,
//    broadcast loads) — no 16KB smem staging phase.
//  - gather uses 4 threads per row: each warp-LDG touches 8 rows (8 wf)
//    instead of 32 (32 wf).
//  - smem ~36KB -> 6 blocks/SM.
__global__ __launch_bounds__(128) void k_mp(int in_id, int out_id, int zero_id,
                                            int iter,
                                            const float* __restrict__ roots,
                                            const float* __restrict__ bias) {
    const float* hin = hsel(in_id);
    float* hout      = hsel(out_id);
    int tid = threadIdx.x;

    if (zero_id >= 0) {
        float4* z = (float4*)hsel(zero_id);
        const int chunk = (ZTOT + GRIDMP - 1) / GRIDMP;
        int lo = blockIdx.x * chunk;
        int hiz = lo + chunk; if (hiz > ZTOT) hiz = ZTOT;
        for (int i = lo + tid; i < hiz; i += 128)
            z[i] = make_float4(0.f, 0.f, 0.f, 0.f);
    }

    __shared__ __align__(16) float hsT[HH][TE + 8];   // [k][row]
    __shared__ int sdst[TE];
    __shared__ int ssrc[TE];

    bool is_root = blockIdx.x < (unsigned)ROOTTILES;
    const float* W;
    int base;

    if (is_root) {
        base = blockIdx.x * TE;
        W = roots + iter * HH * HH;
        {
            int node = base + tid;
            bool ok = node < NN;
            sdst[tid] = ok ? node : -1;
            ssrc[tid] = ok ? node : 0;
        }
    } else {
        int tb = blockIdx.x - ROOTTILES;
        if (tb >= g_tileoff[EDIM]) return;
        int t = 0;
        while (tb >= g_tileoff[t + 1]) t++;
        base = g_toff[t] + (tb - g_tileoff[t]) * TE;
        int hi = g_toff[t + 1];
        W = g_Wmat + t * HH * HH;
        {
            int p = base + tid;
            bool ok = p < hi;
            sdst[tid] = ok ? g_pdst[p] : -1;
            ssrc[tid] = ok ? g_psrc[p] : 0;
        }
    }
    __syncthreads();

    // cooperative gather: 4 threads per row, 32 rows per pass, 4 passes.
    // per warp-LDG: 8 rows x 64B -> 8 wavefronts.
    {
        int q = tid & 3;               // quarter of the row (16 floats)
        int er = tid >> 2;             // 0..31
#pragma unroll
        for (int pass = 0; pass < 4; pass++) {
            int e = pass * 32 + er;
            int s = ssrc[e];
            const float4* hr = (const float4*)(hin + s * HH + q * 16);
#pragma unroll
            for (int j = 0; j < 4; j++) {
                float4 v = hr[j];
                int k = q * 16 + j * 4;
                hsT[k + 0][e] = v.x;
                hsT[k + 1][e] = v.y;
                hsT[k + 2][e] = v.z;
                hsT[k + 3][e] = v.w;
            }
        }
    }
    __syncthreads();

    int rg = tid >> 3;   // 0..15 row group (8 rows = 4 row-pairs)
    int og = tid & 7;    // 0..7  out group (8 outs)

    u64 acc2[4][8];
    if (is_root) {
        float4 b0 = *(const float4*)(bias + iter * HH + og * 8);
        float4 b1 = *(const float4*)(bias + iter * HH + og * 8 + 4);
        float bb[8] = {b0.x, b0.y, b0.z, b0.w, b1.x, b1.y, b1.z, b1.w};
#pragma unroll
        for (int ap = 0; ap < 4; ap++)
#pragma unroll
            for (int b = 0; b < 8; b++) acc2[ap][b] = pack2(bb[b]);
    } else {
#pragma unroll
        for (int ap = 0; ap < 4; ap++)
#pragma unroll
            for (int b = 0; b < 8; b++) acc2[ap][b] = 0ull;
    }

    const float4* Wv = (const float4*)(W + og * 8);   // row k: Wv[k*16], Wv[k*16+1]

#pragma unroll 4
    for (int k = 0; k < HH; k++) {
        double2 ha = *(const double2*)&hsT[k][rg * 8];
        double2 hb = *(const double2*)&hsT[k][rg * 8 + 4];
        u64 h0 = __double_as_longlong(ha.x);
        u64 h1 = __double_as_longlong(ha.y);
        u64 h2 = __double_as_longlong(hb.x);
        u64 h3 = __double_as_longlong(hb.y);
        // w from global (L1-resident, 2-line broadcast per warp)
        float4 w0 = __ldg(Wv + k * 16);
        float4 w1 = __ldg(Wv + k * 16 + 1);
        u64 wb0 = pack2(w0.x), wb1 = pack2(w0.y), wb2 = pack2(w0.z), wb3 = pack2(w0.w);
        u64 wb4 = pack2(w1.x), wb5 = pack2(w1.y), wb6 = pack2(w1.z), wb7 = pack2(w1.w);

        fma2(acc2[0][0], h0, wb0); fma2(acc2[0][1], h0, wb1);
        fma2(acc2[0][2], h0, wb2); fma2(acc2[0][3], h0, wb3);
        fma2(acc2[0][4], h0, wb4); fma2(acc2[0][5], h0, wb5);
        fma2(acc2[0][6], h0, wb6); fma2(acc2[0][7], h0, wb7);

        fma2(acc2[1][0], h1, wb0); fma2(acc2[1][1], h1, wb1);
        fma2(acc2[1][2], h1, wb2); fma2(acc2[1][3], h1, wb3);
        fma2(acc2[1][4], h1, wb4); fma2(acc2[1][5], h1, wb5);
        fma2(acc2[1][6], h1, wb6); fma2(acc2[1][7], h1, wb7);

        fma2(acc2[2][0], h2, wb0); fma2(acc2[2][1], h2, wb1);
        fma2(acc2[2][2], h2, wb2); fma2(acc2[2][3], h2, wb3);
        fma2(acc2[2][4], h2, wb4); fma2(acc2[2][5], h2, wb5);
        fma2(acc2[2][6], h2, wb6); fma2(acc2[2][7], h2, wb7);

        fma2(acc2[3][0], h3, wb0); fma2(acc2[3][1], h3, wb1);
        fma2(acc2[3][2], h3, wb2); fma2(acc2[3][3], h3, wb3);
        fma2(acc2[3][4], h3, wb4); fma2(acc2[3][5], h3, wb5);
        fma2(acc2[3][6], h3, wb6); fma2(acc2[3][7], h3, wb7);
    }

#pragma unroll
    for (int ap = 0; ap < 4; ap++) {
        float2 u0 = unpack2(acc2[ap][0]);
        float2 u1 = unpack2(acc2[ap][1]);
        float2 u2 = unpack2(acc2[ap][2]);
        float2 u3 = unpack2(acc2[ap][3]);
        float2 u4 = unpack2(acc2[ap][4]);
        float2 u5 = unpack2(acc2[ap][5]);
        float2 u6 = unpack2(acc2[ap][6]);
        float2 u7 = unpack2(acc2[ap][7]);
        int dlo = sdst[rg * 8 + 2 * ap];
        int dhi = sdst[rg * 8 + 2 * ap + 1];
        if (dlo >= 0) {
            float* dr = hout + dlo * HH + og * 8;
            red_v4(dr,     u0.x, u1.x, u2.x, u3.x);
            red_v4(dr + 4, u4.x, u5.x, u6.x, u7.x);
        }
        if (dhi >= 0) {
            float* dr = hout + dhi * HH + og * 8;
            red_v4(dr,     u0.y, u1.y, u2.y, u3.y);
            red_v4(dr + 4, u4.y, u5.y, u6.y, u7.y);
        }
    }
}

// ======== fully fused Set2Set: 4 iterations + output MLP ===================
__global__ __launch_bounds__(256) void k_s2s_all(const float* __restrict__ b_ih,
                                                 const float* __restrict__ b_hh,
                                                 const float* __restrict__ W_o1,
                                                 const float* __restrict__ b_o1,
                                                 const float* __restrict__ W_o2,
                                                 const float* __restrict__ b_o2,
                                                 float* __restrict__ out) {
    const float* h = g_hA;          // final node states after MPI=3 (A->B->C->A)
    int b = blockIdx.x;
    int tid = threadIdx.x;

    __shared__ float hcache[SMAX * HH];   // 40KB
    __shared__ float sa[SA];
    __shared__ float qs[2 * HH];
    __shared__ float gates[4 * HH];
    __shared__ float q[HH];
    __shared__ float hx_s[HH];
    __shared__ float cx_s[HH];
    __shared__ float red[256];
    __shared__ float r4[4][HH];

    int s = g_seg[b], t = g_seg[b + 1];
    int len = t - s;
    int nc = len < SMAX ? len : SMAX;

    {
        float4* d4 = (float4*)hcache;
        const float4* s4 = (const float4*)(h + s * HH);
        int tot = nc * (HH / 4);
        for (int i = tid; i < tot; i += 256) d4[i] = s4[i];
    }
    if (tid < 2 * HH) qs[tid] = 0.f;
    if (tid < HH) { hx_s[tid] = 0.f; cx_s[tid] = 0.f; }
    __syncthreads();

    float ev[8];   // per-thread scores (supports len <= 2048)

    for (int it = 0; it < S2S; it++) {
        {
            float g0 = b_ih[tid];
            float g1 = b_hh[tid];
#pragma unroll 8
            for (int k = 0; k < 2 * HH; k++) g0 += qs[k] * g_WihT[k * 256 + tid];
#pragma unroll 8
            for (int k = 0; k < HH; k++)     g1 += hx_s[k] * g_WhhT[k * 256 + tid];
            gates[tid] = g0 + g1;
        }
        __syncthreads();
        if (tid < HH) {
            float ig = gates[tid], fg = gates[HH + tid];
            float gg = gates[2 * HH + tid], og = gates[3 * HH + tid];
            float si = 1.f / (1.f + expf(-ig));
            float sf = 1.f / (1.f + expf(-fg));
            float so = 1.f / (1.f + expf(-og));
            float c = sf * cx_s[tid] + si * tanhf(gg);
            cx_s[tid] = c;
            float hx = so * tanhf(c);
            hx_s[tid] = hx;
            q[tid] = hx;
        }
        __syncthreads();

        float lmax = -1e30f;
        const float4* q4 = (const float4*)q;
        {
            int i = 0;
            for (int l = tid; l < len && i < 8; l += 256, i++) {
                const float4* hr = (l < nc) ? (const float4*)&hcache[l * HH]
                                            : (const float4*)(h + (s + l) * HH);
                float e = 0.f;
#pragma unroll
                for (int k = 0; k < HH / 4; k++) {
                    float4 hv = hr[k];
                    float4 qv = q4[k];
                    e += hv.x * qv.x + hv.y * qv.y + hv.z * qv.z + hv.w * qv.w;
                }
                ev[i] = e;
                lmax = fmaxf(lmax, e);
            }
        }
        red[tid] = lmax; __syncthreads();
        for (int w = 128; w > 0; w >>= 1) {
            if (tid < w) red[tid] = fmaxf(red[tid], red[tid + w]);
            __syncthreads();
        }
        float m = red[0];
        __syncthreads();

        float lsum = 0.f;
        {
            int i = 0;
            for (int l = tid; l < len && i < 8; l += 256, i++) {
                float a = expf(ev[i] - m);
                if (l < SA) sa[l] = a; else g_a[s + l] = a;
                lsum += a;
            }
        }
        red[tid] = lsum; __syncthreads();
        for (int w = 128; w > 0; w >>= 1) {
            if (tid < w) red[tid] += red[tid + w];
            __syncthreads();
        }
        float denom = red[0];
        if (denom == 0.f) denom = 1.f;
        __syncthreads();

        {
            int part = tid >> 6;
            int o = tid & 63;
            float r = 0.f;
            for (int l = part; l < len; l += 4) {
                float av = (l < SA) ? sa[l] : g_a[s + l];
                float hv = (l < nc) ? hcache[l * HH + o] : h[(s + l) * HH + o];
                r += av * hv;
            }
            r4[part][o] = r;
        }
        __syncthreads();
        if (tid < HH) {
            float r = (r4[0][tid] + r4[1][tid] + r4[2][tid] + r4[3][tid]) / denom;
            qs[tid]      = q[tid];
            qs[HH + tid] = r;
        }
        __syncthreads();
    }

    if (tid < HH) {
        float v = b_o1[tid];
#pragma unroll 8
        for (int k = 0; k < 2 * HH; k++) v += qs[k] * W_o1[k * HH + tid];
        v = fmaxf(v, 0.f);
        red[tid] = v * W_o2[tid];
    }
    __syncthreads();
    for (int w = 32; w > 0; w >>= 1) {
        if (tid < w) red[tid] += red[tid + w];
        __syncthreads();
    }
    if (tid == 0) out[b] = red[0] + b_o2[0];
}

// ---------------------------------------------------------------------------
extern "C" void kernel_launch(void* const* d_in, const int* in_sizes, int n_in,
                              void* d_out, int out_size) {
    const float* node_feat = (const float*)d_in[0];
    const int*   node_type = (const int*)d_in[1];
    const int*   edge_index= (const int*)d_in[2];
    const int*   etype     = (const int*)d_in[3];
    const int*   batch     = (const int*)d_in[4];
    const float* W_emb     = (const float*)d_in[5];
    const float* b_emb     = (const float*)d_in[6];
    const float* W_e1      = (const float*)d_in[7];
    const float* b_e1      = (const float*)d_in[8];
    const float* W_e2      = (const float*)d_in[9];
    const float* b_e2      = (const float*)d_in[10];
    const float* roots     = (const float*)d_in[11];
    const float* conv_bias = (const float*)d_in[12];
    const float* W_ih      = (const float*)d_in[13];
    const float* W_hh      = (const float*)d_in[14];
    const float* b_ih      = (const float*)d_in[15];
    const float* b_hh      = (const float*)d_in[16];
    const float* W_o1      = (const float*)d_in[17];
    const float* b_o1      = (const float*)d_in[18];
    const float* W_o2      = (const float*)d_in[19];
    const float* b_o2      = (const float*)d_in[20];
    float* out = (float*)d_out;

    const int* src = edge_index;
    const int* dst = edge_index + EE;

    k_setup<<<(EE + 255) / 256, 256>>>(batch, etype);
    k_front<<<SCB + 66 + NN / 4, 256>>>(etype, src, dst,
                                        W_e1, b_e1, W_e2, b_e2,
                                        node_feat, node_type, W_emb, b_emb,
                                        W_ih, W_hh);

    // 3-buffer rotation: (in, out, zero)
    k_mp<<<GRIDMP, 128>>>(0, 1, 2, 0, roots, conv_bias);  // A->B, zero C
    k_mp<<<GRIDMP, 128>>>(1, 2, 0, 1, roots, conv_bias);  // B->C, zero A
    k_mp<<<GRIDMP, 128>>>(2, 0, -1, 2, roots, conv_bias); // C->A

    k_s2s_all<<<BB, 256>>>(b_ih, b_hh, W_o1, b_o1, W_o2, b_o2, out);
}